// round 4
// baseline (speedup 1.0000x reference)
#include <cuda_runtime.h>
#include <math.h>

#define Bsz 512
#define Tt  1024
#define Dd  64
#define Hh  64
#define NB  4
#define Rr  4
#define MHh 32
#define TCH 512   // t-chunk per proj block
#define PCH 32    // points staged per smem chunk

typedef unsigned long long ull;

// xg[t][b][j] with bias baked in: 512*1024*256 floats = 512MB scratch
__device__ float xg_buf[(size_t)Tt * Bsz * 256];

__device__ __forceinline__ void fma2(ull &d, ull a, ull b){
    asm("fma.rn.f32x2 %0, %1, %2, %0;" : "+l"(d) : "l"(a), "l"(b));
}
__device__ __forceinline__ ull pack2(float lo, float hi){
    ull r; asm("mov.b64 %0, {%1, %2};" : "=l"(r) : "f"(lo), "f"(hi)); return r;
}
__device__ __forceinline__ float2 unpack2(ull v){
    float2 r; asm("mov.b64 {%0, %1}, %2;" : "=f"(r.x), "=f"(r.y) : "l"(v)); return r;
}

__device__ __forceinline__ float fsigmoid(float v){
    return 1.0f / (1.0f + __expf(-v));
}
// Saturation-safe fast tanh: exp argument always <= 0, never overflows.
__device__ __forceinline__ float ftanh(float v){
    float t = __expf(-2.0f * fabsf(v));
    float r = (1.0f - t) / (1.0f + t);
    return copysignf(r, v);
}

// ---------------------------------------------------------------------------
// Input projection: xg[t][b][j] = W_ih[j,:].x[b,t,:] + (b_ih[j]+b_hh[j]).
// 1024 blocks x 256 threads; block = (b, t-chunk of 512). Thread j holds its
// W_ih row in registers; x points staged through smem, broadcast reads.
// Pure parallel FFMA2 work, fma-pipe bound.
// ---------------------------------------------------------------------------
__global__ __launch_bounds__(256)
void proj_kernel(const float* __restrict__ x,
                 const float* __restrict__ W_ih,
                 const float* __restrict__ b_ih,
                 const float* __restrict__ b_hh)
{
    const int j  = threadIdx.x;
    const int b  = blockIdx.x >> 1;
    const int t0 = (blockIdx.x & 1) * TCH;

    __shared__ __align__(16) float xsh[PCH][Dd];

    ull wih[Dd/2];
#pragma unroll
    for (int k = 0; k < Dd/2; k += 2){
        ulonglong2 a = *(const ulonglong2*)&W_ih[j * Dd + 2*k];
        wih[k] = a.x; wih[k+1] = a.y;
    }
    const float bj = b_ih[j] + b_hh[j];

    for (int c0 = 0; c0 < TCH; c0 += PCH){
        // stage PCH x-points (coalesced float4)
        const float4* src = (const float4*)(x + ((size_t)b * Tt + t0 + c0) * Dd);
        float4* dst = (float4*)&xsh[0][0];
#pragma unroll
        for (int i = 0; i < (PCH*Dd/4)/256; i++)
            dst[j + i*256] = src[j + i*256];
        __syncthreads();

#pragma unroll 4
        for (int p = 0; p < PCH; p++){
            const ulonglong2* v = (const ulonglong2*)&xsh[p][0];
            ull a0 = 0ULL, a1 = 0ULL;
#pragma unroll
            for (int q = 0; q < 16; q++){        // 16 * 4 floats = 64
                ulonglong2 w = v[q];             // broadcast LDS.128
                fma2(a0, wih[2*q    ], w.x);
                fma2(a1, wih[2*q + 1], w.y);
            }
            float2 p0 = unpack2(a0), p1 = unpack2(a1);
            xg_buf[((size_t)(t0 + c0 + p) * Bsz + b) * 256 + j] =
                bj + ((p0.x + p1.x) + (p0.y + p1.y));
        }
        __syncthreads();
    }
}

// ---------------------------------------------------------------------------
// Recurrence only: gates = xg[t,b,j] + W_hh[j,:].h. 128 blocks x 256 threads,
// NB=4 batches/block. Thread j owns gate-row j (W_hh row in 64 regs) and the
// state of (batch=j>>6, unit=j&63). xg register-prefetched one step ahead.
// ---------------------------------------------------------------------------
__global__ __launch_bounds__(256, 1)
void lstm_rec_kernel(const float* __restrict__ h_init,
                     const float* __restrict__ c_init,
                     const float* __restrict__ W_hh,
                     float* __restrict__ y)
{
    const int j    = threadIdx.x;
    const int u    = j & 63;
    const int gate = j >> 6;
    const int b0   = blockIdx.x * NB;

    __shared__ __align__(16) float hs[NB][Hh];
    __shared__ float gact[NB][256];

    ull whh[Hh/2];
#pragma unroll
    for (int k = 0; k < Hh/2; k += 2){
        ulonglong2 c = *(const ulonglong2*)&W_hh[j * Hh + 2*k];
        whh[k] = c.x; whh[k+1] = c.y;
    }

    float creg = c_init[u];
    hs[gate][u] = h_init[u];

    float xn[NB];
#pragma unroll
    for (int b = 0; b < NB; b++)
        xn[b] = xg_buf[(size_t)(b0 + b) * 256 + j];   // t = 0
    __syncthreads();

    for (int t = 0; t < Tt; t++){
        float cur[NB];
#pragma unroll
        for (int b = 0; b < NB; b++) cur[b] = xn[b];
        if (t + 1 < Tt){
#pragma unroll
            for (int b = 0; b < NB; b++)
                xn[b] = xg_buf[((size_t)(t + 1) * Bsz + b0 + b) * 256 + j];
        }

        ull a0[NB], a1[NB];
#pragma unroll
        for (int b = 0; b < NB; b++){ a0[b] = 0ULL; a1[b] = 0ULL; }

#pragma unroll
        for (int k = 0; k < Hh; k += 4){
#pragma unroll
            for (int b = 0; b < NB; b++){
                ulonglong2 v = *(const ulonglong2*)&hs[b][k];   // broadcast
                fma2(a0[b], whh[k/2    ], v.x);
                fma2(a1[b], whh[k/2 + 1], v.y);
            }
        }

#pragma unroll
        for (int b = 0; b < NB; b++){
            float2 p0 = unpack2(a0[b]);
            float2 p1 = unpack2(a1[b]);
            float g = cur[b] + ((p0.x + p1.x) + (p0.y + p1.y));
            gact[b][j] = (gate == 2) ? ftanh(g) : fsigmoid(g);
        }
        __syncthreads();

        // state update distributed over all 256 threads: (batch=gate, unit=u)
        {
            float ig = gact[gate][      u];
            float fg = gact[gate][ 64 + u];
            float gg = gact[gate][128 + u];
            float og = gact[gate][192 + u];
            float cn = fmaf(fg, creg, ig * gg);
            creg = cn;
            float hn = og * ftanh(cn);
            hs[gate][u] = hn;
            y[((size_t)(b0 + gate)) * Tt * Hh + (size_t)t * Hh + u] = hn;
        }
        __syncthreads();
    }
}

// ---------------------------------------------------------------------------
// Heads: unchanged from round 3 (register-resident y/h1/h2, FFMA2, weights
// broadcast from shared).
// ---------------------------------------------------------------------------
__global__ __launch_bounds__(128, 2)
void heads_kernel(const float* __restrict__ y,
                  const float* __restrict__ W1, const float* __restrict__ b1,
                  const float* __restrict__ W2, const float* __restrict__ b2,
                  const float* __restrict__ W3, const float* __restrict__ b3,
                  float* __restrict__ outs)
{
    extern __shared__ float sm[];
    float* W1s = sm;
    float* W2s = W1s + 8192;
    float* W3s = W2s + 4096;
    float* b1s = W3s + 128;
    float* b2s = b1s + 128;
    float* b3s = b2s + 128;
    float* ys  = b3s + 8;            // 64 * 133

    const int tid    = threadIdx.x;
    const size_t bt0 = (size_t)blockIdx.x * 128;
    const size_t BT  = (size_t)Bsz * Tt;

    for (int i = tid; i < Rr*MHh*Hh;  i += 128) W1s[i] = W1[i];
    for (int i = tid; i < Rr*MHh*MHh; i += 128) W2s[i] = W2[i];
    if (tid < Rr*MHh){ W3s[tid] = W3[tid]; b1s[tid] = b1[tid]; b2s[tid] = b2[tid]; }
    if (tid < Rr) b3s[tid] = b3[tid];

    for (int i = tid; i < 128 * Hh; i += 128){
        int btl = i >> 6;
        int h   = i & 63;
        ys[h * 133 + btl] = y[bt0 * Hh + i];
    }
    __syncthreads();

    ull yv[Hh/2];
#pragma unroll
    for (int k = 0; k < Hh/2; k++)
        yv[k] = pack2(ys[(2*k) * 133 + tid], ys[(2*k+1) * 133 + tid]);

    for (int r = 0; r < Rr; r++){
        ull h1p[MHh/2];
#pragma unroll
        for (int m = 0; m < MHh; m += 2){
            float hm[2];
#pragma unroll
            for (int mm = 0; mm < 2; mm++){
                const ulonglong2* w = (const ulonglong2*)(W1s + (r*MHh + m + mm) * Hh);
                ull a0 = 0ULL, a1 = 0ULL;
#pragma unroll
                for (int q = 0; q < 16; q++){
                    ulonglong2 ww = w[q];
                    fma2(a0, ww.x, yv[2*q    ]);
                    fma2(a1, ww.y, yv[2*q + 1]);
                }
                float2 p0 = unpack2(a0), p1 = unpack2(a1);
                hm[mm] = fmaxf(b1s[r*MHh + m + mm] + ((p0.x + p1.x) + (p0.y + p1.y)), 0.0f);
            }
            h1p[m/2] = pack2(hm[0], hm[1]);
        }

        ull h2p[MHh/2];
#pragma unroll
        for (int n = 0; n < MHh; n += 2){
            float hv[2];
#pragma unroll
            for (int nn = 0; nn < 2; nn++){
                const ulonglong2* w = (const ulonglong2*)(W2s + (r*MHh + n + nn) * MHh);
                ull a0 = 0ULL, a1 = 0ULL;
#pragma unroll
                for (int q = 0; q < 8; q++){
                    ulonglong2 ww = w[q];
                    fma2(a0, ww.x, h1p[2*q    ]);
                    fma2(a1, ww.y, h1p[2*q + 1]);
                }
                float2 p0 = unpack2(a0), p1 = unpack2(a1);
                hv[nn] = fmaxf(b2s[r*MHh + n + nn] + ((p0.x + p1.x) + (p0.y + p1.y)), 0.0f);
            }
            h2p[n/2] = pack2(hv[0], hv[1]);
        }

        const ulonglong2* w3 = (const ulonglong2*)(W3s + r * MHh);
        ull a0 = 0ULL, a1 = 0ULL;
#pragma unroll
        for (int q = 0; q < 8; q++){
            ulonglong2 ww = w3[q];
            fma2(a0, ww.x, h2p[2*q    ]);
            fma2(a1, ww.y, h2p[2*q + 1]);
        }
        float2 p0 = unpack2(a0), p1 = unpack2(a1);
        outs[(size_t)r * BT + bt0 + tid] = b3s[r] + ((p0.x + p1.x) + (p0.y + p1.y));
    }
}

extern "C" void kernel_launch(void* const* d_in, const int* in_sizes, int n_in,
                              void* d_out, int out_size)
{
    const float* x      = (const float*)d_in[0];
    const float* h_init = (const float*)d_in[1];
    const float* c_init = (const float*)d_in[2];
    const float* W_ih   = (const float*)d_in[3];
    const float* W_hh   = (const float*)d_in[4];
    const float* b_ih   = (const float*)d_in[5];
    const float* b_hh   = (const float*)d_in[6];
    const float* W1     = (const float*)d_in[7];
    const float* b1     = (const float*)d_in[8];
    const float* W2     = (const float*)d_in[9];
    const float* b2     = (const float*)d_in[10];
    const float* W3     = (const float*)d_in[11];
    const float* b3     = (const float*)d_in[12];

    float* y    = (float*)d_out;                     // (B, T, H)
    float* outs = y + (size_t)Bsz * Tt * Hh;         // (R, B, T)

    proj_kernel<<<Bsz * (Tt / TCH), 256>>>(x, W_ih, b_ih, b_hh);

    lstm_rec_kernel<<<Bsz / NB, 256>>>(h_init, c_init, W_hh, y);

    const size_t shmem = 21192 * sizeof(float);
    cudaFuncSetAttribute(heads_kernel,
                         cudaFuncAttributeMaxDynamicSharedMemorySize, (int)shmem);
    heads_kernel<<<(Bsz * Tt) / 128, 128, shmem>>>(y, W1, b1, W2, b2, W3, b3, outs);
}

// round 5
// speedup vs baseline: 1.2303x; 1.2303x over previous
#include <cuda_runtime.h>
#include <math.h>

#define Bsz 512
#define Tt  1024
#define Dd  64
#define Hh  64
#define NB  4
#define Rr  4
#define MHh 32
#define PCH 16    // x points staged per smem chunk (proj)

typedef unsigned long long ull;

// xg[t][b][j] with bias baked in: 512MB scratch
__device__ float xg_buf[(size_t)Tt * Bsz * 256];

__device__ __forceinline__ void fma2(ull &d, ull a, ull b){
    asm("fma.rn.f32x2 %0, %1, %2, %0;" : "+l"(d) : "l"(a), "l"(b));
}
__device__ __forceinline__ ull pack2(float lo, float hi){
    ull r; asm("mov.b64 %0, {%1, %2};" : "=l"(r) : "f"(lo), "f"(hi)); return r;
}
__device__ __forceinline__ float2 unpack2(ull v){
    float2 r; asm("mov.b64 {%0, %1}, %2;" : "=f"(r.x), "=f"(r.y) : "l"(v)); return r;
}

// Fast activations: EX2 + MUFU.RCP (no div.rn Newton sequences).
__device__ __forceinline__ float fsigmoid(float v){
    float e = __expf(-v);
    return __fdividef(1.0f, 1.0f + e);
}
// Saturation-safe: exp argument always <= 0.
__device__ __forceinline__ float ftanh(float v){
    float t = __expf(-2.0f * fabsf(v));
    float r = __fdividef(1.0f - t, 1.0f + t);
    return copysignf(r, v);
}

// ---------------------------------------------------------------------------
// Input projection v2: register-tiled 2 rows/thread.
// 2048 blocks x 128 threads; block = (b, 256-t chunk). Thread j owns weight
// rows j and j+128 (128 regs); each LDS.128 of x feeds 4 fma2 (1:4 ratio).
// ---------------------------------------------------------------------------
__global__ __launch_bounds__(128)
void proj_kernel(const float* __restrict__ x,
                 const float* __restrict__ W_ih,
                 const float* __restrict__ b_ih,
                 const float* __restrict__ b_hh)
{
    const int j  = threadIdx.x;               // 0..127
    const int b  = blockIdx.x >> 2;
    const int t0 = (blockIdx.x & 3) * 256;

    __shared__ __align__(16) float xsh[PCH][Dd];

    ull w0[Dd/2], w1[Dd/2];
#pragma unroll
    for (int k = 0; k < Dd/2; k += 2){
        ulonglong2 a = *(const ulonglong2*)&W_ih[j * Dd + 2*k];
        w0[k] = a.x; w0[k+1] = a.y;
        ulonglong2 c = *(const ulonglong2*)&W_ih[(j + 128) * Dd + 2*k];
        w1[k] = c.x; w1[k+1] = c.y;
    }
    const float bj0 = b_ih[j      ] + b_hh[j      ];
    const float bj1 = b_ih[j + 128] + b_hh[j + 128];

    for (int c0 = 0; c0 < 256; c0 += PCH){
        // stage PCH points: 256 float4, 128 threads -> 2 each
        const float4* src = (const float4*)(x + ((size_t)b * Tt + t0 + c0) * Dd);
        float4* dst = (float4*)&xsh[0][0];
        dst[j] = src[j];
        dst[j + 128] = src[j + 128];
        __syncthreads();

#pragma unroll 2
        for (int p = 0; p < PCH; p++){
            const ulonglong2* v = (const ulonglong2*)&xsh[p][0];
            ull a00 = 0ULL, a01 = 0ULL, a10 = 0ULL, a11 = 0ULL;
#pragma unroll
            for (int q = 0; q < 16; q++){          // 16 x 16B = 64 floats
                ulonglong2 xx = v[q];              // broadcast LDS.128
                fma2(a00, w0[2*q    ], xx.x);
                fma2(a01, w0[2*q + 1], xx.y);
                fma2(a10, w1[2*q    ], xx.x);
                fma2(a11, w1[2*q + 1], xx.y);
            }
            float2 p0 = unpack2(a00), p1 = unpack2(a01);
            float2 p2 = unpack2(a10), p3 = unpack2(a11);
            size_t base = ((size_t)(t0 + c0 + p) * Bsz + b) * 256;
            xg_buf[base + j      ] = bj0 + ((p0.x + p1.x) + (p0.y + p1.y));
            xg_buf[base + 128 + j] = bj1 + ((p2.x + p3.x) + (p2.y + p3.y));
        }
        __syncthreads();
    }
}

// ---------------------------------------------------------------------------
// Recurrence: gates = xg[t,b,j] + W_hh[j,:].h. 128 blocks x 256 threads,
// NB=4 batches/block. Thread j owns gate-row j (W_hh row in regs) and the
// state of (batch=j>>6, unit=j&63). xg register-prefetched one step ahead.
// ---------------------------------------------------------------------------
__global__ __launch_bounds__(256, 1)
void lstm_rec_kernel(const float* __restrict__ h_init,
                     const float* __restrict__ c_init,
                     const float* __restrict__ W_hh,
                     float* __restrict__ y)
{
    const int j    = threadIdx.x;
    const int u    = j & 63;
    const int gate = j >> 6;
    const int b0   = blockIdx.x * NB;

    __shared__ __align__(16) float hs[NB][Hh];
    __shared__ float gact[NB][256];

    ull whh[Hh/2];
#pragma unroll
    for (int k = 0; k < Hh/2; k += 2){
        ulonglong2 c = *(const ulonglong2*)&W_hh[j * Hh + 2*k];
        whh[k] = c.x; whh[k+1] = c.y;
    }

    float creg = c_init[u];
    hs[gate][u] = h_init[u];

    float xn[NB];
#pragma unroll
    for (int b = 0; b < NB; b++)
        xn[b] = xg_buf[(size_t)(b0 + b) * 256 + j];   // t = 0
    __syncthreads();

#pragma unroll 1
    for (int t = 0; t < Tt; t++){
        float cur[NB];
#pragma unroll
        for (int b = 0; b < NB; b++) cur[b] = xn[b];
        if (t + 1 < Tt){
#pragma unroll
            for (int b = 0; b < NB; b++)
                xn[b] = xg_buf[((size_t)(t + 1) * Bsz + b0 + b) * 256 + j];
        }

        ull a0[NB], a1[NB];
#pragma unroll
        for (int b = 0; b < NB; b++){ a0[b] = 0ULL; a1[b] = 0ULL; }

#pragma unroll
        for (int k = 0; k < Hh; k += 4){
#pragma unroll
            for (int b = 0; b < NB; b++){
                ulonglong2 v = *(const ulonglong2*)&hs[b][k];   // broadcast
                fma2(a0[b], whh[k/2    ], v.x);
                fma2(a1[b], whh[k/2 + 1], v.y);
            }
        }

#pragma unroll
        for (int b = 0; b < NB; b++){
            float2 p0 = unpack2(a0[b]);
            float2 p1 = unpack2(a1[b]);
            float g = cur[b] + ((p0.x + p1.x) + (p0.y + p1.y));
            gact[b][j] = (gate == 2) ? ftanh(g) : fsigmoid(g);
        }
        __syncthreads();

        // state update distributed over all 256 threads: (batch=gate, unit=u)
        {
            float ig = gact[gate][      u];
            float fg = gact[gate][ 64 + u];
            float gg = gact[gate][128 + u];
            float og = gact[gate][192 + u];
            float cn = fmaf(fg, creg, ig * gg);
            creg = cn;
            float hn = og * ftanh(cn);
            hs[gate][u] = hn;
            y[((size_t)(b0 + gate)) * Tt * Hh + (size_t)t * Hh + u] = hn;
        }
        __syncthreads();
    }
}

// ---------------------------------------------------------------------------
// Heads: register-resident y/h1/h2, FFMA2, weights broadcast from shared.
// 4 accumulator chains per dot product for ILP; float4 y staging.
// ---------------------------------------------------------------------------
__global__ __launch_bounds__(128, 2)
void heads_kernel(const float* __restrict__ y,
                  const float* __restrict__ W1, const float* __restrict__ b1,
                  const float* __restrict__ W2, const float* __restrict__ b2,
                  const float* __restrict__ W3, const float* __restrict__ b3,
                  float* __restrict__ outs)
{
    extern __shared__ float sm[];
    float* W1s = sm;
    float* W2s = W1s + 8192;
    float* W3s = W2s + 4096;
    float* b1s = W3s + 128;
    float* b2s = b1s + 128;
    float* b3s = b2s + 128;
    float* ys  = b3s + 8;            // 64 * 133

    const int tid    = threadIdx.x;
    const size_t bt0 = (size_t)blockIdx.x * 128;
    const size_t BT  = (size_t)Bsz * Tt;

    for (int i = tid; i < Rr*MHh*Hh;  i += 128) W1s[i] = W1[i];
    for (int i = tid; i < Rr*MHh*MHh; i += 128) W2s[i] = W2[i];
    if (tid < Rr*MHh){ W3s[tid] = W3[tid]; b1s[tid] = b1[tid]; b2s[tid] = b2[tid]; }
    if (tid < Rr) b3s[tid] = b3[tid];

    // stage y tile transposed, float4 gmem reads
    {
        const float4* ysrc = (const float4*)(y + bt0 * Hh);
#pragma unroll
        for (int it = 0; it < 16; it++){
            int i4  = tid + it * 128;
            float4 v = ysrc[i4];
            int btl = i4 >> 4;
            int h   = (i4 & 15) * 4;
            ys[(h+0)*133 + btl] = v.x;
            ys[(h+1)*133 + btl] = v.y;
            ys[(h+2)*133 + btl] = v.z;
            ys[(h+3)*133 + btl] = v.w;
        }
    }
    __syncthreads();

    ull yv[Hh/2];
#pragma unroll
    for (int k = 0; k < Hh/2; k++)
        yv[k] = pack2(ys[(2*k) * 133 + tid], ys[(2*k+1) * 133 + tid]);

    for (int r = 0; r < Rr; r++){
        ull h1p[MHh/2];
#pragma unroll
        for (int m = 0; m < MHh; m += 2){
            float hm[2];
#pragma unroll
            for (int mm = 0; mm < 2; mm++){
                const ulonglong2* w = (const ulonglong2*)(W1s + (r*MHh + m + mm) * Hh);
                ull a0 = 0ULL, a1 = 0ULL, a2 = 0ULL, a3 = 0ULL;
#pragma unroll
                for (int q = 0; q < 8; q++){        // 8 x 2 ulonglong2 = 64 floats
                    ulonglong2 wa = w[2*q    ];
                    ulonglong2 wb = w[2*q + 1];
                    fma2(a0, wa.x, yv[4*q    ]);
                    fma2(a1, wa.y, yv[4*q + 1]);
                    fma2(a2, wb.x, yv[4*q + 2]);
                    fma2(a3, wb.y, yv[4*q + 3]);
                }
                float2 p0 = unpack2(a0), p1 = unpack2(a1);
                float2 p2 = unpack2(a2), p3 = unpack2(a3);
                float s = ((p0.x + p1.x) + (p0.y + p1.y)) + ((p2.x + p3.x) + (p2.y + p3.y));
                hm[mm] = fmaxf(b1s[r*MHh + m + mm] + s, 0.0f);
            }
            h1p[m/2] = pack2(hm[0], hm[1]);
        }

        ull h2p[MHh/2];
#pragma unroll
        for (int n = 0; n < MHh; n += 2){
            float hv[2];
#pragma unroll
            for (int nn = 0; nn < 2; nn++){
                const ulonglong2* w = (const ulonglong2*)(W2s + (r*MHh + n + nn) * MHh);
                ull a0 = 0ULL, a1 = 0ULL, a2 = 0ULL, a3 = 0ULL;
#pragma unroll
                for (int q = 0; q < 4; q++){        // 4 x 2 ulonglong2 = 32 floats
                    ulonglong2 wa = w[2*q    ];
                    ulonglong2 wb = w[2*q + 1];
                    fma2(a0, wa.x, h1p[4*q    ]);
                    fma2(a1, wa.y, h1p[4*q + 1]);
                    fma2(a2, wb.x, h1p[4*q + 2]);
                    fma2(a3, wb.y, h1p[4*q + 3]);
                }
                float2 p0 = unpack2(a0), p1 = unpack2(a1);
                float2 p2 = unpack2(a2), p3 = unpack2(a3);
                float s = ((p0.x + p1.x) + (p0.y + p1.y)) + ((p2.x + p3.x) + (p2.y + p3.y));
                hv[nn] = fmaxf(b2s[r*MHh + n + nn] + s, 0.0f);
            }
            h2p[n/2] = pack2(hv[0], hv[1]);
        }

        const ulonglong2* w3 = (const ulonglong2*)(W3s + r * MHh);
        ull a0 = 0ULL, a1 = 0ULL, a2 = 0ULL, a3 = 0ULL;
#pragma unroll
        for (int q = 0; q < 4; q++){
            ulonglong2 wa = w3[2*q    ];
            ulonglong2 wb = w3[2*q + 1];
            fma2(a0, wa.x, h2p[4*q    ]);
            fma2(a1, wa.y, h2p[4*q + 1]);
            fma2(a2, wb.x, h2p[4*q + 2]);
            fma2(a3, wb.y, h2p[4*q + 3]);
        }
        float2 p0 = unpack2(a0), p1 = unpack2(a1);
        float2 p2 = unpack2(a2), p3 = unpack2(a3);
        float s = ((p0.x + p1.x) + (p0.y + p1.y)) + ((p2.x + p3.x) + (p2.y + p3.y));
        outs[(size_t)r * BT + bt0 + tid] = b3s[r] + s;
    }
}

extern "C" void kernel_launch(void* const* d_in, const int* in_sizes, int n_in,
                              void* d_out, int out_size)
{
    const float* x      = (const float*)d_in[0];
    const float* h_init = (const float*)d_in[1];
    const float* c_init = (const float*)d_in[2];
    const float* W_ih   = (const float*)d_in[3];
    const float* W_hh   = (const float*)d_in[4];
    const float* b_ih   = (const float*)d_in[5];
    const float* b_hh   = (const float*)d_in[6];
    const float* W1     = (const float*)d_in[7];
    const float* b1     = (const float*)d_in[8];
    const float* W2     = (const float*)d_in[9];
    const float* b2     = (const float*)d_in[10];
    const float* W3     = (const float*)d_in[11];
    const float* b3     = (const float*)d_in[12];

    float* y    = (float*)d_out;                     // (B, T, H)
    float* outs = y + (size_t)Bsz * Tt * Hh;         // (R, B, T)

    proj_kernel<<<Bsz * 4, 128>>>(x, W_ih, b_ih, b_hh);

    lstm_rec_kernel<<<Bsz / NB, 256>>>(h_init, c_init, W_hh, y);

    const size_t shmem = 21192 * sizeof(float);
    cudaFuncSetAttribute(heads_kernel,
                         cudaFuncAttributeMaxDynamicSharedMemorySize, (int)shmem);
    heads_kernel<<<(Bsz * Tt) / 128, 128, shmem>>>(y, W1, b1, W2, b2, W3, b3, outs);
}